// round 2
// baseline (speedup 1.0000x reference)
#include <cuda_runtime.h>

// AR(3), 2 dims, diagonal alpha. 4096 trials x 8192 steps.
// out[trial][t][d], t<3: = x_0 exactly.
// t>=3: x[t,d] = a0d*x[t-3,d] + a1d*x[t-2,d] + a2d*x[t-1,d] + noise'[t-3,d]
// noise'[s,0] = s0*n0 + (mu0 + xmu0*(1-sum a_d0))
// noise'[s,1] = rho*s1*n0 + sqrt(1-rho^2)*s1*n1 + (mu1 + xmu1*(1-sum a_d1))

#define N_TRIALS 4096
#define N_STEPS  8192
#define N_ORDER  3
#define N_NOISE  (N_STEPS - N_ORDER)   // 8189
#define G        16                    // trials per block
#define TT       256                   // time-tile steps
#define NTHREADS 128
#define PITCH    (2*G + 2)             // 34 floats: conflict-free float2 pitch

__global__ __launch_bounds__(NTHREADS)
void arma_kernel(const float* __restrict__ alpha,
                 const float* __restrict__ xmu,
                 const float* __restrict__ sigma,
                 const float* __restrict__ rho_p,
                 const float* __restrict__ mu,
                 const float* __restrict__ x_0,
                 const float* __restrict__ normals,
                 float* __restrict__ out)
{
    __shared__ float sm[TT * PITCH];   // time-major noise/result tile

    const int tid = threadIdx.x;
    const int tb  = blockIdx.x * G;    // first trial of this block

    // ---- parameters (tiny, L1/L2 cached) ----
    const float a00 = alpha[0], a01 = alpha[1];   // alpha[k][d], k row-major
    const float a10 = alpha[2], a11 = alpha[3];
    const float a20 = alpha[4], a21 = alpha[5];
    const float s0  = sigma[0], s1 = sigma[1];
    const float rho = rho_p[0];
    const float c10 = rho * s1;
    const float c11 = sqrtf(1.0f - rho * rho) * s1;
    const float k0  = mu[0] + xmu[0] * (1.0f - a00 - a10 - a20);
    const float k1  = mu[1] + xmu[1] * (1.0f - a01 - a11 - a21);

    // ---- first ORDER outputs = x_0 verbatim ----
    if (tid < G * N_ORDER * 2) {
        int g = tid / (N_ORDER * 2);
        int r = tid % (N_ORDER * 2);
        out[(size_t)(tb + g) * N_STEPS * 2 + r] =
            x_0[(size_t)(tb + g) * N_ORDER * 2 + r];
    }

    // ---- per-chain recurrence state (threads 0..2G-1) ----
    const int gg = tid >> 1;      // trial within block
    const int dd = tid & 1;       // dim
    float xs0 = 0.f, xs1 = 0.f, xs2 = 0.f, aa0 = 0.f, aa1 = 0.f, aa2 = 0.f;
    if (tid < 2 * G) {
        const float* xp = x_0 + (size_t)(tb + gg) * N_ORDER * 2 + dd;
        xs0 = xp[0]; xs1 = xp[2]; xs2 = xp[4];   // oldest..newest
        aa0 = dd ? a01 : a00;
        aa1 = dd ? a11 : a10;
        aa2 = dd ? a21 : a20;
    }

    for (int t0 = 0; t0 < N_NOISE; t0 += TT) {
        const int n = min(TT, N_NOISE - t0);

        // ---- phase 1: coalesced load + noise transform -> smem (time-major).
        // s outer, g inner fully unrolled: 16 independent LDG.64 in flight
        // per thread per position -> MLP ~16 hides DRAM latency. ----
        for (int s = tid; s < n; s += NTHREADS) {
            #pragma unroll
            for (int g = 0; g < G; ++g) {
                const float2* src =
                    (const float2*)(normals + (size_t)(tb + g) * N_NOISE * 2) + t0;
                float2 v = src[s];
                float e0 = fmaf(s0, v.x, k0);
                float e1 = fmaf(c10, v.x, fmaf(c11, v.y, k1));
                *(float2*)&sm[s * PITCH + 2 * g] = make_float2(e0, e1);
            }
        }
        __syncthreads();

        // ---- phase 2: sequential recurrence, in-place (threads 0..31).
        // unroll 3 matches the AR(3) lag period -> lag shuffle is pure
        // register renaming, no MOVs; 1 dependent FFMA chain. ----
        if (tid < 2 * G) {
            float* p = sm + 2 * gg + dd;
            #pragma unroll 3
            for (int s = 0; s < n; ++s) {
                float nz = p[s * PITCH];
                float x  = fmaf(aa2, xs2, fmaf(aa1, xs1, fmaf(aa0, xs0, nz)));
                p[s * PITCH] = x;
                xs0 = xs1; xs1 = xs2; xs2 = x;
            }
        }
        __syncthreads();

        // ---- phase 3: coalesced flush smem -> out ----
        for (int s = tid; s < n; s += NTHREADS) {
            #pragma unroll
            for (int g = 0; g < G; ++g) {
                float2* dst =
                    (float2*)(out + (size_t)(tb + g) * N_STEPS * 2) + (t0 + N_ORDER);
                dst[s] = *(float2*)&sm[s * PITCH + 2 * g];
            }
        }
        __syncthreads();
    }
}

extern "C" void kernel_launch(void* const* d_in, const int* in_sizes, int n_in,
                              void* d_out, int out_size)
{
    const float* alpha   = (const float*)d_in[0];
    const float* xmu     = (const float*)d_in[1];
    const float* sigma   = (const float*)d_in[2];
    const float* rho     = (const float*)d_in[3];
    const float* mu      = (const float*)d_in[4];
    const float* x_0     = (const float*)d_in[5];
    const float* normals = (const float*)d_in[6];
    float* out = (float*)d_out;

    arma_kernel<<<N_TRIALS / G, NTHREADS>>>(alpha, xmu, sigma, rho, mu,
                                            x_0, normals, out);
}